// round 3
// baseline (speedup 1.0000x reference)
#include <cuda_runtime.h>
#include <cuda_bf16.h>

// Problem constants
#define M_ROWS   4096          // b*NT*2*NO = 16*8*32
#define K_VIS    2048
#define FEAT     512
#define BT       128           // b*NT
#define NO       16
#define TGT      24
#define N_EDGE   (BT * NO * NO)        // 32768
#define OUT_LOGITS (N_EDGE * TGT)      // 786432

// Scratch (device globals: no allocation allowed; referenced ONLY in device code)
__device__ float g_h1[M_ROWS * FEAT];
__device__ float g_h2[M_ROWS * FEAT];
__device__ float g_node[M_ROWS * FEAT];
__device__ float g_sout[BT * NO * TGT];
__device__ float g_oout[BT * NO * TGT];
__device__ float g_p1[128];
__device__ float g_p2[128];
__device__ int   g_tgt_is64;

// ---------------------------------------------------------------------------
// Tiled SGEMM: C[M,N] = A[M,K] @ B[K,N] + bias[N], optional ReLU.
// BM=BN=128, BK=8, 256 threads, 8x8 per-thread microtile.
// STAGE selects scratch buffers (host cannot take device-global addresses):
//   STAGE 0: A = Aparam (src), C = g_h1, ReLU
//   STAGE 1: A = g_h1,         C = g_h2
//   STAGE 2: A = g_h2,         C = g_node
// ---------------------------------------------------------------------------
template <int STAGE>
__global__ __launch_bounds__(256) void sgemm128(
    const float* __restrict__ Aparam, const float* __restrict__ B,
    const float* __restrict__ bias,
    int M, int N, int K)
{
    const float* __restrict__ A =
        (STAGE == 0) ? Aparam : (STAGE == 1 ? g_h1 : g_h2);
    float* __restrict__ C =
        (STAGE == 0) ? g_h1 : (STAGE == 1 ? g_h2 : g_node);

    __shared__ float As[8][128];   // transposed A tile: As[k][m]
    __shared__ float Bs[8][128];

    const int tid = threadIdx.x;
    const int bm = blockIdx.y * 128;
    const int bn = blockIdx.x * 128;

    const int ty = tid >> 4;       // 0..15
    const int tx = tid & 15;       // 0..15

    // A tile load indices: 128x8 floats = 256 float4 (one per thread)
    const int aRow = tid >> 1;          // 0..127
    const int aCol = (tid & 1) * 4;     // 0 or 4
    // B tile load indices: 8x128 floats
    const int bRow = tid >> 5;          // 0..7
    const int bCol = (tid & 31) * 4;    // 0..124

    const float* Ap = A + (size_t)(bm + aRow) * K + aCol;
    const float* Bp = B + (size_t)bRow * N + bn + bCol;

    float acc[8][8];
#pragma unroll
    for (int i = 0; i < 8; i++)
#pragma unroll
        for (int j = 0; j < 8; j++) acc[i][j] = 0.0f;

    for (int k0 = 0; k0 < K; k0 += 8) {
        float4 a4 = *reinterpret_cast<const float4*>(Ap);  Ap += 8;
        float4 b4 = *reinterpret_cast<const float4*>(Bp);  Bp += (size_t)8 * N;

        As[aCol + 0][aRow] = a4.x;
        As[aCol + 1][aRow] = a4.y;
        As[aCol + 2][aRow] = a4.z;
        As[aCol + 3][aRow] = a4.w;
        *reinterpret_cast<float4*>(&Bs[bRow][bCol]) = b4;
        __syncthreads();

#pragma unroll
        for (int k = 0; k < 8; k++) {
            float4 ra0 = *reinterpret_cast<const float4*>(&As[k][ty * 8]);
            float4 ra1 = *reinterpret_cast<const float4*>(&As[k][ty * 8 + 4]);
            float4 rb0 = *reinterpret_cast<const float4*>(&Bs[k][tx * 8]);
            float4 rb1 = *reinterpret_cast<const float4*>(&Bs[k][tx * 8 + 4]);
            float ra[8] = {ra0.x, ra0.y, ra0.z, ra0.w, ra1.x, ra1.y, ra1.z, ra1.w};
            float rb[8] = {rb0.x, rb0.y, rb0.z, rb0.w, rb1.x, rb1.y, rb1.z, rb1.w};
#pragma unroll
            for (int i = 0; i < 8; i++)
#pragma unroll
                for (int j = 0; j < 8; j++)
                    acc[i][j] = fmaf(ra[i], rb[j], acc[i][j]);
        }
        __syncthreads();
    }

    // Epilogue: bias (+ReLU for STAGE 0) and store
#pragma unroll
    for (int i = 0; i < 8; i++) {
        const int row = bm + ty * 8 + i;
        float* crow = C + (size_t)row * N + bn + tx * 8;
#pragma unroll
        for (int j = 0; j < 8; j++) {
            float v = acc[i][j] + bias[bn + tx * 8 + j];
            if (STAGE == 0) v = fmaxf(v, 0.0f);
            crow[j] = v;
        }
    }
}

// ---------------------------------------------------------------------------
// Rel-head small GEMM: node row r (4096 rows of FEAT=512),
// within-frame index n<NO -> subject (dot with wr[0:512,:]),
// else object (dot with wr[512:1024,:]). 24 logits per row.
// One warp per row, 8 rows/block; wr half staged in smem (48KB).
// ---------------------------------------------------------------------------
__global__ __launch_bounds__(256) void rel_small_kernel(
    const float* __restrict__ wr)
{
    __shared__ float ws[FEAT * TGT];   // 49152 bytes
    const int base = blockIdx.x * 8;               // 8 rows per block
    const bool subj = ((base & 31) < NO);          // whole block same type
    const float* wsel = wr + (subj ? 0 : FEAT) * TGT;
    for (int i = threadIdx.x; i < FEAT * TGT; i += 256) ws[i] = wsel[i];
    __syncthreads();

    const int w = threadIdx.x >> 5;
    const int lane = threadIdx.x & 31;
    const int r = base + w;
    const float* nr = g_node + (size_t)r * FEAT;

    float v[16];
#pragma unroll
    for (int i = 0; i < 16; i++) v[i] = nr[lane + 32 * i];

    float acc[TGT];
#pragma unroll
    for (int t = 0; t < TGT; t++) acc[t] = 0.0f;

#pragma unroll
    for (int i = 0; i < 16; i++) {
        const float* wrow = &ws[(lane + 32 * i) * TGT];
#pragma unroll
        for (int t = 0; t < TGT; t++) acc[t] = fmaf(v[i], wrow[t], acc[t]);
    }

#pragma unroll
    for (int t = 0; t < TGT; t++) {
#pragma unroll
        for (int off = 16; off > 0; off >>= 1)
            acc[t] += __shfl_xor_sync(0xFFFFFFFFu, acc[t], off);
    }

    const int bt = r >> 5;
    const int n = r & 31;
    float* dst = subj ? (g_sout + (size_t)(bt * NO + n) * TGT)
                      : (g_oout + (size_t)(bt * NO + (n - NO)) * TGT);
    if (lane < TGT) dst[lane] = acc[lane];
}

// ---------------------------------------------------------------------------
// Edge combine: out[bt, i*NO+j, t] = sout[bt,i,t] + oout[bt,j,t] + br[t]
// ---------------------------------------------------------------------------
__global__ __launch_bounds__(256) void combine_kernel(
    const float* __restrict__ br, float* __restrict__ out)
{
    const int idx = blockIdx.x * blockDim.x + threadIdx.x;
    if (idx >= OUT_LOGITS) return;
    const int t = idx % TGT;
    const int e = (idx / TGT) & 255;          // NO*NO = 256
    const int bt = idx / (TGT * NO * NO);
    const int i = e >> 4;
    const int j = e & 15;
    out[idx] = g_sout[(size_t)(bt * NO + i) * TGT + t]
             + g_oout[(size_t)(bt * NO + j) * TGT + t] + br[t];
}

// ---------------------------------------------------------------------------
// Target dtype detection: int64 vs int32 (JAX x64-disabled silently downcasts).
// For int64 LE with values in [0,24), every odd 32-bit word is 0.
// Reads only first 128 words (512 B) -> in bounds under either dtype.
// ---------------------------------------------------------------------------
__global__ void detect_tgt_kernel(const int* __restrict__ tgt32)
{
    int allzero = 1;
    for (int i = 1; i < 128; i += 2)
        if (tgt32[i] != 0) { allzero = 0; break; }
    g_tgt_is64 = allzero;
}

// ---------------------------------------------------------------------------
// Loss stage 1: per-row weighted NLL, deterministic block reduction.
// Also writes tgt as float into d_out. 128 blocks x 256 threads = 32768 rows.
// ---------------------------------------------------------------------------
__global__ __launch_bounds__(256) void loss_part_kernel(
    const float* __restrict__ out, const int* __restrict__ tgt32,
    float* __restrict__ tgtf)
{
    const int r = blockIdx.x * blockDim.x + threadIdx.x;
    const float* row = out + (size_t)r * TGT;
    float m = row[0];
#pragma unroll
    for (int t = 1; t < TGT; t++) m = fmaxf(m, row[t]);
    float s = 0.0f;
#pragma unroll
    for (int t = 0; t < TGT; t++) s += expf(row[t] - m);
    const int tg = g_tgt_is64 ? tgt32[2 * r] : tgt32[r];
    const float nll = logf(s) + m - row[tg];
    const float w = (tg == 0) ? 1.0f : 100.0f;
    tgtf[r] = (float)tg;

    __shared__ float sh1[256], sh2[256];
    sh1[threadIdx.x] = w * nll;
    sh2[threadIdx.x] = w;
    __syncthreads();
    for (int off = 128; off > 0; off >>= 1) {
        if (threadIdx.x < off) {
            sh1[threadIdx.x] += sh1[threadIdx.x + off];
            sh2[threadIdx.x] += sh2[threadIdx.x + off];
        }
        __syncthreads();
    }
    if (threadIdx.x == 0) { g_p1[blockIdx.x] = sh1[0]; g_p2[blockIdx.x] = sh2[0]; }
}

__global__ __launch_bounds__(128) void loss_final_kernel(float* __restrict__ loss)
{
    __shared__ float sh1[128], sh2[128];
    sh1[threadIdx.x] = g_p1[threadIdx.x];
    sh2[threadIdx.x] = g_p2[threadIdx.x];
    __syncthreads();
    for (int off = 64; off > 0; off >>= 1) {
        if (threadIdx.x < off) {
            sh1[threadIdx.x] += sh1[threadIdx.x + off];
            sh2[threadIdx.x] += sh2[threadIdx.x + off];
        }
        __syncthreads();
    }
    if (threadIdx.x == 0) loss[0] = sh1[0] / sh2[0];
}

// ---------------------------------------------------------------------------
extern "C" void kernel_launch(void* const* d_in, const int* in_sizes, int n_in,
                              void* d_out, int out_size)
{
    const float* src   = (const float*)d_in[0];
    const int*   tgt32 = (const int*)d_in[1];
    const float* w1 = (const float*)d_in[2];
    const float* b1 = (const float*)d_in[3];
    const float* w2 = (const float*)d_in[4];
    const float* b2 = (const float*)d_in[5];
    const float* wf = (const float*)d_in[6];
    const float* bf = (const float*)d_in[7];
    const float* wr = (const float*)d_in[8];
    const float* br = (const float*)d_in[9];
    float* out = (float*)d_out;

    dim3 grid_g(FEAT / 128, M_ROWS / 128);   // (4, 32)

    detect_tgt_kernel<<<1, 1>>>(tgt32);
    // MLP: g_h1 = relu(src @ w1 + b1)
    sgemm128<0><<<grid_g, 256>>>(src, w1, b1, M_ROWS, FEAT, K_VIS);
    // g_h2 = g_h1 @ w2 + b2
    sgemm128<1><<<grid_g, 256>>>(nullptr, w2, b2, M_ROWS, FEAT, FEAT);
    // g_node = g_h2 @ wf + bf
    sgemm128<2><<<grid_g, 256>>>(nullptr, wf, bf, M_ROWS, FEAT, FEAT);
    // rel head halves
    rel_small_kernel<<<M_ROWS / 8, 256>>>(wr);
    // edge logits -> d_out[0 : 786432]
    combine_kernel<<<(OUT_LOGITS + 255) / 256, 256>>>(br, out);
    // loss partials + tgt floats -> d_out[786432 : 819200]
    loss_part_kernel<<<128, 256>>>(out, tgt32, out + OUT_LOGITS);
    // loss scalar -> d_out[819200]
    loss_final_kernel<<<1, 128>>>(out + OUT_LOGITS + N_EDGE);
}

// round 4
// speedup vs baseline: 1.2196x; 1.2196x over previous
#include <cuda_runtime.h>
#include <cuda_bf16.h>

// Problem constants
#define M_ROWS   4096          // b*NT*2*NO = 16*8*32
#define K_VIS    2048
#define FEAT     512
#define BT       128           // b*NT
#define NO       16
#define TGT      24
#define N_EDGE   (BT * NO * NO)        // 32768
#define OUT_LOGITS (N_EDGE * TGT)      // 786432

// Scratch (device globals; referenced ONLY in device code)
__device__ float g_h1[M_ROWS * FEAT];
__device__ float g_h2[M_ROWS * FEAT];
__device__ float g_node[M_ROWS * FEAT];
__device__ float g_sout[BT * NO * TGT];
__device__ float g_oout[BT * NO * TGT];
__device__ float g_p1[128];
__device__ float g_p2[128];
__device__ int   g_tgt_is64;

// ---------------------------------------------------------------------------
// Packed fp32x2 helpers (second FP32 datapath on sm_103a is only reachable
// via PTX fma.rn.f32x2 — ptxas never emits FFMA2 from scalar C++).
// ---------------------------------------------------------------------------
__device__ __forceinline__ void ffma2(unsigned long long& d,
                                      unsigned long long a,
                                      unsigned long long b) {
    asm("fma.rn.f32x2 %0, %1, %2, %0;" : "+l"(d) : "l"(a), "l"(b));
}
__device__ __forceinline__ unsigned long long bcast2(float v) {
    unsigned long long r;
    asm("mov.b64 %0, {%1, %1};" : "=l"(r) : "f"(v));
    return r;
}
__device__ __forceinline__ void unpack2(float& lo, float& hi,
                                        unsigned long long v) {
    asm("mov.b64 {%0, %1}, %2;" : "=f"(lo), "=f"(hi) : "l"(v));
}

// ---------------------------------------------------------------------------
// FFMA2 SGEMM: C[M,N] = A[M,K] @ B[K,N] + bias[N], optional ReLU.
// BM=128, BN=64, BK=8, 256 threads, 8(M)x4(N) per-thread microtile with
// accumulators packed in pairs along M. Double-buffered smem, 1 sync/tile.
// STAGE: 0: A=param(src) C=g_h1 (ReLU); 1: A=g_h1 C=g_h2; 2: A=g_h2 C=g_node
// ---------------------------------------------------------------------------
#define BM 128
#define BN 64
#define BK 8
#define AS_STRIDE 132   // padded to kill STS bank conflicts; 132*4B is 16B-aligned

template <int STAGE>
__global__ __launch_bounds__(256) void sgemm_f32x2(
    const float* __restrict__ Aparam, const float* __restrict__ B,
    const float* __restrict__ bias, int M, int N, int K)
{
    const float* __restrict__ A =
        (STAGE == 0) ? Aparam : (STAGE == 1 ? g_h1 : g_h2);
    float* __restrict__ C =
        (STAGE == 0) ? g_h1 : (STAGE == 1 ? g_h2 : g_node);

    __shared__ float As[2][BK][AS_STRIDE];   // transposed: As[k][m]
    __shared__ float Bs[2][BK][BN];

    const int tid = threadIdx.x;
    const int bm = blockIdx.y * BM;
    const int bn = blockIdx.x * BN;

    const int ty = tid >> 4;        // 0..15 -> rows ty*8
    const int tx = tid & 15;        // 0..15 -> cols tx*4

    // A tile: 128x8 floats = 256 float4 -> 1 per thread
    const int aRow = tid >> 1;          // 0..127
    const int aCol = (tid & 1) * 4;     // 0 or 4
    // B tile: 8x64 floats = 128 float4 -> threads 0..127
    const int bRow = tid >> 4;          // 0..15 (only <8 used via tid<128)
    const int bCol = (tid & 15) * 4;

    const float* Ap = A + (size_t)(bm + aRow) * K + aCol;
    const float* Bp = B + (size_t)bRow * N + bn + bCol;
    const bool bAct = (tid < 128);

    unsigned long long acc[4][4];       // [i2][j]: lo=row 2*i2, hi=row 2*i2+1
#pragma unroll
    for (int i = 0; i < 4; i++)
#pragma unroll
        for (int j = 0; j < 4; j++) acc[i][j] = 0ull;

    const int nTiles = K / BK;

    // Prologue: load tile 0 and stage into smem buffer 0
    float4 aReg = *reinterpret_cast<const float4*>(Ap);
    float4 bReg = bAct ? *reinterpret_cast<const float4*>(Bp)
                       : make_float4(0.f, 0.f, 0.f, 0.f);
    As[0][aCol + 0][aRow] = aReg.x;
    As[0][aCol + 1][aRow] = aReg.y;
    As[0][aCol + 2][aRow] = aReg.z;
    As[0][aCol + 3][aRow] = aReg.w;
    if (bAct) *reinterpret_cast<float4*>(&Bs[0][bRow][bCol]) = bReg;
    __syncthreads();

    for (int t = 0; t < nTiles; t++) {
        const int cur = t & 1;
        const bool more = (t + 1 < nTiles);
        if (more) {
            Ap += BK;
            aReg = *reinterpret_cast<const float4*>(Ap);
            if (bAct) {
                Bp += (size_t)BK * N;
                bReg = *reinterpret_cast<const float4*>(Bp);
            }
        }

#pragma unroll
        for (int k = 0; k < BK; k++) {
            // 8 consecutive A values for this thread's rows -> 4 packed pairs
            const ulonglong2 a01 =
                *reinterpret_cast<const ulonglong2*>(&As[cur][k][ty * 8]);
            const ulonglong2 a23 =
                *reinterpret_cast<const ulonglong2*>(&As[cur][k][ty * 8 + 4]);
            unsigned long long ap[4] = {a01.x, a01.y, a23.x, a23.y};

            const float4 b4 =
                *reinterpret_cast<const float4*>(&Bs[cur][k][tx * 4]);
            unsigned long long bp[4] = {bcast2(b4.x), bcast2(b4.y),
                                        bcast2(b4.z), bcast2(b4.w)};
#pragma unroll
            for (int i = 0; i < 4; i++)
#pragma unroll
                for (int j = 0; j < 4; j++)
                    ffma2(acc[i][j], ap[i], bp[j]);
        }

        if (more) {
            const int nxt = cur ^ 1;
            As[nxt][aCol + 0][aRow] = aReg.x;
            As[nxt][aCol + 1][aRow] = aReg.y;
            As[nxt][aCol + 2][aRow] = aReg.z;
            As[nxt][aCol + 3][aRow] = aReg.w;
            if (bAct) *reinterpret_cast<float4*>(&Bs[nxt][bRow][bCol]) = bReg;
            __syncthreads();
        }
    }

    // Epilogue: bias (+ReLU for STAGE 0), STG.128 per row
    const float4 bi = *reinterpret_cast<const float4*>(&bias[bn + tx * 4]);
#pragma unroll
    for (int i2 = 0; i2 < 4; i2++) {
        float4 lo, hi;
        unpack2(lo.x, hi.x, acc[i2][0]);
        unpack2(lo.y, hi.y, acc[i2][1]);
        unpack2(lo.z, hi.z, acc[i2][2]);
        unpack2(lo.w, hi.w, acc[i2][3]);
        lo.x += bi.x; lo.y += bi.y; lo.z += bi.z; lo.w += bi.w;
        hi.x += bi.x; hi.y += bi.y; hi.z += bi.z; hi.w += bi.w;
        if (STAGE == 0) {
            lo.x = fmaxf(lo.x, 0.f); lo.y = fmaxf(lo.y, 0.f);
            lo.z = fmaxf(lo.z, 0.f); lo.w = fmaxf(lo.w, 0.f);
            hi.x = fmaxf(hi.x, 0.f); hi.y = fmaxf(hi.y, 0.f);
            hi.z = fmaxf(hi.z, 0.f); hi.w = fmaxf(hi.w, 0.f);
        }
        const int r0 = bm + ty * 8 + 2 * i2;
        *reinterpret_cast<float4*>(C + (size_t)r0 * N + bn + tx * 4) = lo;
        *reinterpret_cast<float4*>(C + (size_t)(r0 + 1) * N + bn + tx * 4) = hi;
    }
}

// ---------------------------------------------------------------------------
// Rel-head small GEMM: node row r (4096 rows of FEAT=512),
// within-frame index n<NO -> subject (wr[0:512,:]), else object (wr[512:,:]).
// One warp per row, 8 rows/block; wr half staged in smem (48KB).
// ---------------------------------------------------------------------------
__global__ __launch_bounds__(256) void rel_small_kernel(
    const float* __restrict__ wr)
{
    __shared__ float ws[FEAT * TGT];   // 49152 bytes
    const int base = blockIdx.x * 8;
    const bool subj = ((base & 31) < NO);
    const float* wsel = wr + (subj ? 0 : FEAT) * TGT;
    for (int i = threadIdx.x; i < FEAT * TGT; i += 256) ws[i] = wsel[i];
    __syncthreads();

    const int w = threadIdx.x >> 5;
    const int lane = threadIdx.x & 31;
    const int r = base + w;
    const float* nr = g_node + (size_t)r * FEAT;

    float v[16];
#pragma unroll
    for (int i = 0; i < 16; i++) v[i] = nr[lane + 32 * i];

    float acc[TGT];
#pragma unroll
    for (int t = 0; t < TGT; t++) acc[t] = 0.0f;

#pragma unroll
    for (int i = 0; i < 16; i++) {
        const float* wrow = &ws[(lane + 32 * i) * TGT];
#pragma unroll
        for (int t = 0; t < TGT; t++) acc[t] = fmaf(v[i], wrow[t], acc[t]);
    }

#pragma unroll
    for (int t = 0; t < TGT; t++) {
#pragma unroll
        for (int off = 16; off > 0; off >>= 1)
            acc[t] += __shfl_xor_sync(0xFFFFFFFFu, acc[t], off);
    }

    const int bt = r >> 5;
    const int n = r & 31;
    float* dst = subj ? (g_sout + (size_t)(bt * NO + n) * TGT)
                      : (g_oout + (size_t)(bt * NO + (n - NO)) * TGT);
    if (lane < TGT) dst[lane] = acc[lane];
}

// ---------------------------------------------------------------------------
// Edge combine: out[bt, i*NO+j, t] = sout[bt,i,t] + oout[bt,j,t] + br[t]
// ---------------------------------------------------------------------------
__global__ __launch_bounds__(256) void combine_kernel(
    const float* __restrict__ br, float* __restrict__ out)
{
    const int idx = blockIdx.x * blockDim.x + threadIdx.x;
    if (idx >= OUT_LOGITS) return;
    const int t = idx % TGT;
    const int e = (idx / TGT) & 255;          // NO*NO = 256
    const int bt = idx / (TGT * NO * NO);
    const int i = e >> 4;
    const int j = e & 15;
    out[idx] = g_sout[(size_t)(bt * NO + i) * TGT + t]
             + g_oout[(size_t)(bt * NO + j) * TGT + t] + br[t];
}

// ---------------------------------------------------------------------------
// Target dtype detection: int64 vs int32 (JAX x64-disabled downcasts).
// ---------------------------------------------------------------------------
__global__ void detect_tgt_kernel(const int* __restrict__ tgt32)
{
    int allzero = 1;
    for (int i = 1; i < 128; i += 2)
        if (tgt32[i] != 0) { allzero = 0; break; }
    g_tgt_is64 = allzero;
}

// ---------------------------------------------------------------------------
// Loss stage 1: per-row weighted NLL, deterministic block reduction.
// ---------------------------------------------------------------------------
__global__ __launch_bounds__(256) void loss_part_kernel(
    const float* __restrict__ out, const int* __restrict__ tgt32,
    float* __restrict__ tgtf)
{
    const int r = blockIdx.x * blockDim.x + threadIdx.x;
    const float* row = out + (size_t)r * TGT;
    float m = row[0];
#pragma unroll
    for (int t = 1; t < TGT; t++) m = fmaxf(m, row[t]);
    float s = 0.0f;
#pragma unroll
    for (int t = 0; t < TGT; t++) s += expf(row[t] - m);
    const int tg = g_tgt_is64 ? tgt32[2 * r] : tgt32[r];
    const float nll = logf(s) + m - row[tg];
    const float w = (tg == 0) ? 1.0f : 100.0f;
    tgtf[r] = (float)tg;

    __shared__ float sh1[256], sh2[256];
    sh1[threadIdx.x] = w * nll;
    sh2[threadIdx.x] = w;
    __syncthreads();
    for (int off = 128; off > 0; off >>= 1) {
        if (threadIdx.x < off) {
            sh1[threadIdx.x] += sh1[threadIdx.x + off];
            sh2[threadIdx.x] += sh2[threadIdx.x + off];
        }
        __syncthreads();
    }
    if (threadIdx.x == 0) { g_p1[blockIdx.x] = sh1[0]; g_p2[blockIdx.x] = sh2[0]; }
}

__global__ __launch_bounds__(128) void loss_final_kernel(float* __restrict__ loss)
{
    __shared__ float sh1[128], sh2[128];
    sh1[threadIdx.x] = g_p1[threadIdx.x];
    sh2[threadIdx.x] = g_p2[threadIdx.x];
    __syncthreads();
    for (int off = 64; off > 0; off >>= 1) {
        if (threadIdx.x < off) {
            sh1[threadIdx.x] += sh1[threadIdx.x + off];
            sh2[threadIdx.x] += sh2[threadIdx.x + off];
        }
        __syncthreads();
    }
    if (threadIdx.x == 0) loss[0] = sh1[0] / sh2[0];
}

// ---------------------------------------------------------------------------
extern "C" void kernel_launch(void* const* d_in, const int* in_sizes, int n_in,
                              void* d_out, int out_size)
{
    const float* src   = (const float*)d_in[0];
    const int*   tgt32 = (const int*)d_in[1];
    const float* w1 = (const float*)d_in[2];
    const float* b1 = (const float*)d_in[3];
    const float* w2 = (const float*)d_in[4];
    const float* b2 = (const float*)d_in[5];
    const float* wf = (const float*)d_in[6];
    const float* bf = (const float*)d_in[7];
    const float* wr = (const float*)d_in[8];
    const float* br = (const float*)d_in[9];
    float* out = (float*)d_out;

    dim3 grid_g(FEAT / BN, M_ROWS / BM);   // (8, 32) = 256 CTAs

    detect_tgt_kernel<<<1, 1>>>(tgt32);
    // g_h1 = relu(src @ w1 + b1)
    sgemm_f32x2<0><<<grid_g, 256>>>(src, w1, b1, M_ROWS, FEAT, K_VIS);
    // g_h2 = g_h1 @ w2 + b2
    sgemm_f32x2<1><<<grid_g, 256>>>(nullptr, w2, b2, M_ROWS, FEAT, FEAT);
    // g_node = g_h2 @ wf + bf
    sgemm_f32x2<2><<<grid_g, 256>>>(nullptr, wf, bf, M_ROWS, FEAT, FEAT);
    // rel head halves
    rel_small_kernel<<<M_ROWS / 8, 256>>>(wr);
    // edge logits -> d_out[0 : 786432]
    combine_kernel<<<(OUT_LOGITS + 255) / 256, 256>>>(br, out);
    // loss partials + tgt floats -> d_out[786432 : 819200]
    loss_part_kernel<<<128, 256>>>(out, tgt32, out + OUT_LOGITS);
    // loss scalar -> d_out[819200]
    loss_final_kernel<<<1, 128>>>(out + OUT_LOGITS + N_EDGE);
}